// round 5
// baseline (speedup 1.0000x reference)
#include <cuda_runtime.h>
#include <cuda_fp16.h>
#include <cstdint>

// Problem shape (fixed)
#define S_TOK 2048
#define K_DIM 4096
#define O_DIM 4096
#define NGRP  32

// GEMM tiling
#define BM 128
#define BN 128
#define BK 128                 // one quant group per k-iter
#define NKT (K_DIM / BK)       // 32
#define THREADS 256            // 8 warps: 2 (M) x 4 (N), warp tile 64x32
#define NSTAGE 4

// Device-global scratch (no runtime allocation allowed)
__device__ __align__(128) unsigned char g_xq[(size_t)S_TOK * K_DIM]; // u8 codes q in [0,255]
__device__ float g_xscale[S_TOK];
__device__ float g_xzp[S_TOK];
__device__ __align__(128) signed char g_wq[(size_t)O_DIM * K_DIM];   // s8 centered codes in [-15,15]
__device__ float g_wT[O_DIM];                                        // T_o = sum_g s_og * sum_c w'

// ---------------------------------------------------------------------------
// Kernel 1: per-token asymmetric activation quantization -> u8 codes
// ---------------------------------------------------------------------------
__global__ __launch_bounds__(256) void quant_act_kernel(const float* __restrict__ x) {
    const int row = blockIdx.x;
    const int tid = threadIdx.x;
    const float* xr = x + (size_t)row * K_DIM;

    float4 v[4];
    float mn = INFINITY, mx = -INFINITY;
#pragma unroll
    for (int i = 0; i < 4; i++) {
        v[i] = ((const float4*)xr)[tid + i * 256];
        mn = fminf(mn, fminf(fminf(v[i].x, v[i].y), fminf(v[i].z, v[i].w)));
        mx = fmaxf(mx, fmaxf(fmaxf(v[i].x, v[i].y), fmaxf(v[i].z, v[i].w)));
    }
#pragma unroll
    for (int o = 16; o; o >>= 1) {
        mn = fminf(mn, __shfl_xor_sync(0xffffffffu, mn, o));
        mx = fmaxf(mx, __shfl_xor_sync(0xffffffffu, mx, o));
    }
    __shared__ float smn[8], smx[8];
    __shared__ float s_scale, s_zp;
    const int wid = tid >> 5, lane = tid & 31;
    if (lane == 0) { smn[wid] = mn; smx[wid] = mx; }
    __syncthreads();
    if (tid == 0) {
        float a = smn[0], b = smx[0];
#pragma unroll
        for (int i = 1; i < 8; i++) { a = fminf(a, smn[i]); b = fmaxf(b, smx[i]); }
        float sc = fmaxf((b - a) * (1.0f / 255.0f), 1e-5f);
        float zp = fminf(fmaxf(rintf(-a / sc), 0.0f), 255.0f);
        s_scale = sc; s_zp = zp;
        g_xscale[row] = sc;
        g_xzp[row] = zp;
    }
    __syncthreads();
    const float sc = s_scale, zp = s_zp;

    unsigned char* outp = g_xq + (size_t)row * K_DIM;
#pragma unroll
    for (int i = 0; i < 4; i++) {
        uchar4 u;
        u.x = (unsigned char)(fminf(fmaxf(rintf(v[i].x / sc) + zp, 0.0f), 255.0f));
        u.y = (unsigned char)(fminf(fmaxf(rintf(v[i].y / sc) + zp, 0.0f), 255.0f));
        u.z = (unsigned char)(fminf(fmaxf(rintf(v[i].z / sc) + zp, 0.0f), 255.0f));
        u.w = (unsigned char)(fminf(fmaxf(rintf(v[i].w / sc) + zp, 0.0f), 255.0f));
        ((uchar4*)outp)[tid + i * 256] = u;
    }
}

// ---------------------------------------------------------------------------
// Kernel 2: weight repack int32 codes -> s8 (code - zp), plus T_o precompute
// ---------------------------------------------------------------------------
__global__ __launch_bounds__(256) void dequant_w_kernel(
    const int* __restrict__ qw, const float* __restrict__ wsc, const int* __restrict__ wzp)
{
    const int o = blockIdx.x;
    const int t = threadIdx.x;
    const int g = t >> 3;                    // 8 threads per 128-code group
    const float s = wsc[o * NGRP + g];
    const int   z = wzp[o * NGRP + g];
    const int4* src = (const int4*)(qw + (size_t)o * K_DIM + t * 16);

    int packed[4];
    int psum = 0;
#pragma unroll
    for (int j = 0; j < 4; j++) {
        int4 c = src[j];
        int w0 = c.x - z, w1 = c.y - z, w2 = c.z - z, w3 = c.w - z;
        psum += w0 + w1 + w2 + w3;
        packed[j] = (w0 & 0xFF) | ((w1 & 0xFF) << 8) | ((w2 & 0xFF) << 16) | ((w3 & 0xFF) << 24);
    }
    *(int4*)(g_wq + (size_t)o * K_DIM + t * 16) = *(int4*)packed;

    // group sum reduction over the 8 threads of this group
#pragma unroll
    for (int off = 4; off; off >>= 1) psum += __shfl_down_sync(0xffffffffu, psum, off, 8);

    __shared__ float sT[32];
    if ((t & 7) == 0) sT[g] = s * (float)psum;
    __syncthreads();
    if (t == 0) {
        float T = 0.f;
#pragma unroll
        for (int i = 0; i < 32; i++) T += sT[i];
        g_wT[o] = T;
    }
}

// ---------------------------------------------------------------------------
// Kernel 3: u8 x s8 IMMA GEMM, 128x128 tile, BK=128, 4-stage cp.async,
//           per-group fp32 rescale, zero-point-corrected epilogue
// ---------------------------------------------------------------------------
#define IMMA16832(d, a0, a1, a2, a3, b0, b1)                                       \
    asm volatile(                                                                  \
        "mma.sync.aligned.m16n8k32.row.col.s32.u8.s8.s32 "                         \
        "{%0,%1,%2,%3},{%4,%5,%6,%7},{%8,%9},{%0,%1,%2,%3};"                       \
        : "+r"(d[0]), "+r"(d[1]), "+r"(d[2]), "+r"(d[3])                           \
        : "r"(a0), "r"(a1), "r"(a2), "r"(a3), "r"(b0), "r"(b1))

__device__ __forceinline__ void cp_async16(uint32_t saddr, const void* g) {
    asm volatile("cp.async.cg.shared.global [%0], [%1], 16;" :: "r"(saddr), "l"(g));
}
#define CP_COMMIT() asm volatile("cp.async.commit_group;")

// rows of 128 bytes; 16B chunk c swizzled by row
__device__ __forceinline__ uint32_t sw(int r, int c) {
    return (uint32_t)(r * 128 + ((c ^ (r & 7)) << 4));
}

#define SC_BYTES (NGRP * BN * 4)             // 16384: all group scales for this bn
#define A_BYTES  (BM * BK)                   // 16384
#define B_BYTES  (BN * BK)                   // 16384
#define STAGE_BYTES (A_BYTES + B_BYTES)      // 32768
#define GEMM_SMEM (SC_BYTES + NSTAGE * STAGE_BYTES)   // 147456

extern __shared__ char smem_raw[];

__global__ __launch_bounds__(THREADS, 1) void gemm_i8_kernel(
    const float* __restrict__ w_scales,
    const float* __restrict__ bias, float* __restrict__ out)
{
    const int tid  = threadIdx.x;
    const int warp = tid >> 5, lane = tid & 31;
    const int warp_m = warp & 1;   // 2 along M (64 rows)
    const int warp_n = warp >> 1;  // 4 along N (32 cols)
    const int bm = (blockIdx.x & 15) * BM;   // m fastest -> weight L2 reuse
    const int bn = (blockIdx.x >> 4) * BN;

    float* Ssc = (float*)smem_raw;                       // [NGRP][BN]
    const uint32_t sbase = (uint32_t)__cvta_generic_to_shared(smem_raw) + SC_BYTES;

    // preload all group scales for this CTA's 128 columns (coalesced on g)
#pragma unroll
    for (int i = 0; i < 16; i++) {
        const int idx = tid + i * 256;      // 4096 scales
        const int col = idx >> 5, g = idx & 31;
        Ssc[g * BN + col] = w_scales[(size_t)(bn + col) * NGRP + g];
    }

    const unsigned char* gA = g_xq + (size_t)bm * K_DIM;
    const signed char*   gB = g_wq + (size_t)bn * K_DIM;

    auto load_stage = [&](int s, int kt) {
        const uint32_t a_s = sbase + s * STAGE_BYTES;
        const uint32_t b_s = a_s + A_BYTES;
        const size_t koff = (size_t)kt * BK;
#pragma unroll
        for (int i = 0; i < 4; i++) {       // A: 1024 x 16B chunks
            const int ch = tid + i * 256;
            const int r = ch >> 3, c = ch & 7;
            cp_async16(a_s + sw(r, c), gA + (size_t)r * K_DIM + koff + c * 16);
        }
#pragma unroll
        for (int i = 0; i < 4; i++) {       // B: 1024 x 16B chunks
            const int ch = tid + i * 256;
            const int r = ch >> 3, c = ch & 7;
            cp_async16(b_s + sw(r, c), gB + (size_t)r * K_DIM + koff + c * 16);
        }
        CP_COMMIT();
    };

    int   iacc[4][4][4];
    float facc[4][4][4];
#pragma unroll
    for (int i = 0; i < 4; i++)
#pragma unroll
        for (int j = 0; j < 4; j++)
#pragma unroll
            for (int k = 0; k < 4; k++) { iacc[i][j][k] = 0; facc[i][j][k] = 0.f; }

    load_stage(0, 0);
    load_stage(1, 1);
    load_stage(2, 2);

    for (int kt = 0; kt < NKT; kt++) {
        const int s = kt & (NSTAGE - 1);

        if (kt + 3 < NKT) {
            load_stage((kt + 3) & (NSTAGE - 1), kt + 3);
            asm volatile("cp.async.wait_group 3;");
        } else if (kt + 2 < NKT) {
            asm volatile("cp.async.wait_group 2;");
        } else if (kt + 1 < NKT) {
            asm volatile("cp.async.wait_group 1;");
        } else {
            asm volatile("cp.async.wait_group 0;");
        }
        __syncthreads();

        const uint32_t a_s = sbase + s * STAGE_BYTES;
        const uint32_t b_s = a_s + A_BYTES;

#pragma unroll
        for (int ks = 0; ks < 4; ks++) {      // 4 k32-steps in BK=128
            uint32_t af[4][4], bf[2][4];
            const int arow = warp_m * 64 + (lane & 15);
            const int ac   = ks * 2 + (lane >> 4);
#pragma unroll
            for (int mi = 0; mi < 4; mi++) {
                uint32_t addr = a_s + sw(arow + mi * 16, ac);
                asm volatile("ldmatrix.sync.aligned.m8n8.x4.shared.b16 {%0,%1,%2,%3},[%4];"
                             : "=r"(af[mi][0]), "=r"(af[mi][1]),
                               "=r"(af[mi][2]), "=r"(af[mi][3])
                             : "r"(addr));
            }
            const int brow = warp_n * 32 + (lane >> 4) * 8 + (lane & 7);
            const int bc   = ks * 2 + ((lane >> 3) & 1);
#pragma unroll
            for (int nj = 0; nj < 2; nj++) {  // two n16 groups
                uint32_t addr = b_s + sw(brow + nj * 16, bc);
                asm volatile("ldmatrix.sync.aligned.m8n8.x4.shared.b16 {%0,%1,%2,%3},[%4];"
                             : "=r"(bf[nj][0]), "=r"(bf[nj][1]),
                               "=r"(bf[nj][2]), "=r"(bf[nj][3])
                             : "r"(addr));
            }
#pragma unroll
            for (int mi = 0; mi < 4; mi++)
#pragma unroll
                for (int njj = 0; njj < 4; njj++) {
                    const int nj = njj >> 1, h = (njj & 1) * 2;
                    IMMA16832(iacc[mi][njj],
                              af[mi][0], af[mi][1], af[mi][2], af[mi][3],
                              bf[nj][h], bf[nj][h + 1]);
                }
        }

        // per-group rescale: facc += iacc * s(col, g=kt); reset iacc
        const float* srow = Ssc + kt * BN + warp_n * 32 + (lane & 3) * 2;
#pragma unroll
        for (int njj = 0; njj < 4; njj++) {
            const float2 sv = *(const float2*)(srow + njj * 8);
#pragma unroll
            for (int mi = 0; mi < 4; mi++) {
                facc[mi][njj][0] += (float)iacc[mi][njj][0] * sv.x;
                facc[mi][njj][1] += (float)iacc[mi][njj][1] * sv.y;
                facc[mi][njj][2] += (float)iacc[mi][njj][2] * sv.x;
                facc[mi][njj][3] += (float)iacc[mi][njj][3] * sv.y;
                iacc[mi][njj][0] = 0; iacc[mi][njj][1] = 0;
                iacc[mi][njj][2] = 0; iacc[mi][njj][3] = 0;
            }
        }
        __syncthreads();   // all warps done with stage s before it is refilled
    }

    // epilogue: out = (facc - zp_row * T_col) * x_scale_row + bias_col
#pragma unroll
    for (int mi = 0; mi < 4; mi++) {
        const int row0 = bm + warp_m * 64 + mi * 16 + (lane >> 2);
        const int row1 = row0 + 8;
        const float xs0 = g_xscale[row0], zp0 = g_xzp[row0];
        const float xs1 = g_xscale[row1], zp1 = g_xzp[row1];
        float* p0 = out + (size_t)row0 * O_DIM;
        float* p1 = out + (size_t)row1 * O_DIM;
#pragma unroll
        for (int njj = 0; njj < 4; njj++) {
            const int col = bn + warp_n * 32 + njj * 8 + (lane & 3) * 2;
            const float2 bv = *(const float2*)(bias + col);
            const float2 Tv = *(const float2*)(g_wT + col);
            float2 o0, o1;
            o0.x = (facc[mi][njj][0] - zp0 * Tv.x) * xs0 + bv.x;
            o0.y = (facc[mi][njj][1] - zp0 * Tv.y) * xs0 + bv.y;
            o1.x = (facc[mi][njj][2] - zp1 * Tv.x) * xs1 + bv.x;
            o1.y = (facc[mi][njj][3] - zp1 * Tv.y) * xs1 + bv.y;
            *(float2*)(p0 + col) = o0;
            *(float2*)(p1 + col) = o1;
        }
    }
}

// ---------------------------------------------------------------------------
extern "C" void kernel_launch(void* const* d_in, const int* in_sizes, int n_in,
                              void* d_out, int out_size) {
    const float* x        = (const float*)d_in[0];
    const int*   qweight  = (const int*)d_in[1];
    const float* w_scales = (const float*)d_in[2];
    const int*   w_zp     = (const int*)d_in[3];
    const float* bias     = (const float*)d_in[4];
    float*       out      = (float*)d_out;

    quant_act_kernel<<<S_TOK, 256>>>(x);
    dequant_w_kernel<<<O_DIM, 256>>>(qweight, w_scales, w_zp);

    cudaFuncSetAttribute(gemm_i8_kernel,
                         cudaFuncAttributeMaxDynamicSharedMemorySize, GEMM_SMEM);
    const int grid = (S_TOK / BM) * (O_DIM / BN);   // 16 x 32 = 512
    gemm_i8_kernel<<<grid, THREADS, GEMM_SMEM>>>(w_scales, bias, out);
}

// round 6
// speedup vs baseline: 2.9007x; 2.9007x over previous
#include <cuda_runtime.h>
#include <cuda_fp16.h>
#include <cstdint>

// Problem shape (fixed)
#define S_TOK 2048
#define K_DIM 4096
#define O_DIM 4096
#define NGRP  32

// GEMM tiling
#define BM 128
#define BN 128
#define BK 64
#define NKT (K_DIM / BK)     // 64
#define THREADS 256          // 8 warps: 2 (M) x 4 (N), warp tile 64x32
#define NSTAGE 3

// Device-global scratch (no runtime allocation allowed)
__device__ __align__(128) __half g_xq[(size_t)S_TOK * K_DIM];   // centered quantized activations
__device__ float  g_xscale[S_TOK];
__device__ __align__(128) __half g_wq[(size_t)O_DIM * K_DIM];   // dequantized weights (code-zp)*scale

// ---------------------------------------------------------------------------
// Kernel 1: per-token asymmetric activation quantization -> centered fp16
// ---------------------------------------------------------------------------
__global__ __launch_bounds__(256) void quant_act_kernel(const float* __restrict__ x) {
    const int row = blockIdx.x;
    const int tid = threadIdx.x;
    const float* xr = x + (size_t)row * K_DIM;

    float4 v[4];
    float mn = INFINITY, mx = -INFINITY;
#pragma unroll
    for (int i = 0; i < 4; i++) {
        v[i] = ((const float4*)xr)[tid + i * 256];
        mn = fminf(mn, fminf(fminf(v[i].x, v[i].y), fminf(v[i].z, v[i].w)));
        mx = fmaxf(mx, fmaxf(fmaxf(v[i].x, v[i].y), fmaxf(v[i].z, v[i].w)));
    }
#pragma unroll
    for (int o = 16; o; o >>= 1) {
        mn = fminf(mn, __shfl_xor_sync(0xffffffffu, mn, o));
        mx = fmaxf(mx, __shfl_xor_sync(0xffffffffu, mx, o));
    }
    __shared__ float smn[8], smx[8];
    __shared__ float s_scale, s_zp;
    const int wid = tid >> 5, lane = tid & 31;
    if (lane == 0) { smn[wid] = mn; smx[wid] = mx; }
    __syncthreads();
    if (tid == 0) {
        float a = smn[0], b = smx[0];
#pragma unroll
        for (int i = 1; i < 8; i++) { a = fminf(a, smn[i]); b = fmaxf(b, smx[i]); }
        float sc = fmaxf((b - a) * (1.0f / 255.0f), 1e-5f);
        float zp = fminf(fmaxf(rintf(-a / sc), 0.0f), 255.0f);
        s_scale = sc; s_zp = zp;
        g_xscale[row] = sc;
    }
    __syncthreads();
    const float sc = s_scale, zp = s_zp;

    __half* outp = g_xq + (size_t)row * K_DIM;
#pragma unroll
    for (int i = 0; i < 4; i++) {
        float q0 = fminf(fmaxf(rintf(v[i].x / sc) + zp, 0.0f), 255.0f) - zp;
        float q1 = fminf(fmaxf(rintf(v[i].y / sc) + zp, 0.0f), 255.0f) - zp;
        float q2 = fminf(fmaxf(rintf(v[i].z / sc) + zp, 0.0f), 255.0f) - zp;
        float q3 = fminf(fmaxf(rintf(v[i].w / sc) + zp, 0.0f), 255.0f) - zp;
        __half2 p0, p1;
        p0.x = __float2half_rn(q0); p0.y = __float2half_rn(q1);
        p1.x = __float2half_rn(q2); p1.y = __float2half_rn(q3);
        ((__half2*)outp)[(tid + i * 256) * 2 + 0] = p0;
        ((__half2*)outp)[(tid + i * 256) * 2 + 1] = p1;
    }
}

// ---------------------------------------------------------------------------
// Kernel 2: weight dequant int32 codes -> fp16 (code - zp) * scale
// ---------------------------------------------------------------------------
__global__ __launch_bounds__(256) void dequant_w_kernel(
    const int* __restrict__ qw, const float* __restrict__ wsc, const int* __restrict__ wzp)
{
    const int o = blockIdx.x;
    const int t = threadIdx.x;
    const int g = t >> 3;
    const float s = wsc[o * NGRP + g];
    const float z = (float)wzp[o * NGRP + g];
    const int4* src = (const int4*)(qw + (size_t)o * K_DIM + t * 16);
    __half2 h[8];
#pragma unroll
    for (int j = 0; j < 4; j++) {
        int4 c = src[j];
        h[j * 2 + 0].x = __float2half_rn(((float)c.x - z) * s);
        h[j * 2 + 0].y = __float2half_rn(((float)c.y - z) * s);
        h[j * 2 + 1].x = __float2half_rn(((float)c.z - z) * s);
        h[j * 2 + 1].y = __float2half_rn(((float)c.w - z) * s);
    }
    uint4* dst = (uint4*)(g_wq + (size_t)o * K_DIM + t * 16);
    dst[0] = *(uint4*)&h[0];
    dst[1] = *(uint4*)&h[4];
}

// ---------------------------------------------------------------------------
// Kernel 3: fp16 GEMM, 128x128 CTA tile, 64x32 warp tile, 3-stage cp.async,
//           2 CTAs/SM, one barrier per k-iter
// ---------------------------------------------------------------------------
#define MMA16816(d, a0, a1, a2, a3, b0, b1)                                        \
    asm volatile(                                                                  \
        "mma.sync.aligned.m16n8k16.row.col.f32.f16.f16.f32 "                       \
        "{%0,%1,%2,%3},{%4,%5,%6,%7},{%8,%9},{%0,%1,%2,%3};"                       \
        : "+f"(d[0]), "+f"(d[1]), "+f"(d[2]), "+f"(d[3])                           \
        : "r"(a0), "r"(a1), "r"(a2), "r"(a3), "r"(b0), "r"(b1))

__device__ __forceinline__ void cp_async16(uint32_t saddr, const void* g) {
    asm volatile("cp.async.cg.shared.global [%0], [%1], 16;" :: "r"(saddr), "l"(g));
}
#define CP_COMMIT() asm volatile("cp.async.commit_group;")
#define CP_WAIT1()  asm volatile("cp.async.wait_group 1;")

// rows of 64 fp16 = 128B; 16B chunk c swizzled by row
__device__ __forceinline__ uint32_t sw(int r, int c) {
    return (uint32_t)(r * 128 + ((c ^ (r & 7)) << 4));
}

#define A_BYTES (BM * 128)                   // 16384
#define B_BYTES (BN * 128)                   // 16384
#define STAGE_BYTES (A_BYTES + B_BYTES)      // 32768
#define GEMM_SMEM (NSTAGE * STAGE_BYTES)     // 98304 -> 2 CTAs/SM

extern __shared__ char smem_raw[];

__global__ __launch_bounds__(THREADS, 2) void gemm_f16_kernel(
    const float* __restrict__ bias, float* __restrict__ out)
{
    const int tid  = threadIdx.x;
    const int warp = tid >> 5, lane = tid & 31;
    const int warp_m = warp & 1;   // 2 along M (64 rows)
    const int warp_n = warp >> 1;  // 4 along N (32 cols)
    const int bm = (blockIdx.x & 15) * BM;   // m fastest -> weight L2 reuse
    const int bn = (blockIdx.x >> 4) * BN;

    const uint32_t sbase = (uint32_t)__cvta_generic_to_shared(smem_raw);

    const __half* gA = g_xq + (size_t)bm * K_DIM;
    const __half* gB = g_wq + (size_t)bn * K_DIM;

    auto load_stage = [&](int s, int kt) {
        const uint32_t a_s = sbase + s * STAGE_BYTES;
        const uint32_t b_s = a_s + A_BYTES;
        const size_t koff = (size_t)kt * BK;
#pragma unroll
        for (int i = 0; i < 4; i++) {           // A: 1024 chunks of 16B
            const int ch = tid + i * 256;
            const int r = ch >> 3, c = ch & 7;
            cp_async16(a_s + sw(r, c), gA + (size_t)r * K_DIM + koff + c * 8);
        }
#pragma unroll
        for (int i = 0; i < 4; i++) {           // B: 1024 chunks of 16B
            const int ch = tid + i * 256;
            const int r = ch >> 3, c = ch & 7;
            cp_async16(b_s + sw(r, c), gB + (size_t)r * K_DIM + koff + c * 8);
        }
        CP_COMMIT();
    };

    float acc[4][4][4];
#pragma unroll
    for (int i = 0; i < 4; i++)
#pragma unroll
        for (int j = 0; j < 4; j++)
#pragma unroll
            for (int k = 0; k < 4; k++) acc[i][j][k] = 0.f;

    load_stage(0, 0);
    load_stage(1, 1);

    for (int kt = 0; kt < NKT; kt++) {
        const int s = kt % NSTAGE;

        CP_WAIT1();            // stage kt's group retired (only kt+1's may pend)
        __syncthreads();       // cp.async data visible to all; prev stage fully consumed

        // issue next load AFTER barrier: overwrite-safety guaranteed by this barrier
        if (kt + 2 < NKT) {
            load_stage((kt + 2) % NSTAGE, kt + 2);
        } else {
            CP_COMMIT();       // empty group keeps wait_group accounting uniform
        }

        const uint32_t a_s = sbase + s * STAGE_BYTES;
        const uint32_t b_s = a_s + A_BYTES;

#pragma unroll
        for (int ks = 0; ks < 4; ks++) {        // 4 k16 steps in BK=64
            uint32_t af[4][4], bf[2][4];
            const int arow = warp_m * 64 + (lane & 15);
            const int ac   = ks * 2 + (lane >> 4);
#pragma unroll
            for (int mi = 0; mi < 4; mi++) {
                uint32_t addr = a_s + sw(arow + mi * 16, ac);
                asm volatile("ldmatrix.sync.aligned.m8n8.x4.shared.b16 {%0,%1,%2,%3},[%4];"
                             : "=r"(af[mi][0]), "=r"(af[mi][1]),
                               "=r"(af[mi][2]), "=r"(af[mi][3])
                             : "r"(addr));
            }
            const int brow = warp_n * 32 + (lane >> 4) * 8 + (lane & 7);
            const int bc   = ks * 2 + ((lane >> 3) & 1);
#pragma unroll
            for (int nj = 0; nj < 2; nj++) {    // two n16 groups = 32 cols
                uint32_t addr = b_s + sw(brow + nj * 16, bc);
                asm volatile("ldmatrix.sync.aligned.m8n8.x4.shared.b16 {%0,%1,%2,%3},[%4];"
                             : "=r"(bf[nj][0]), "=r"(bf[nj][1]),
                               "=r"(bf[nj][2]), "=r"(bf[nj][3])
                             : "r"(addr));
            }
#pragma unroll
            for (int mi = 0; mi < 4; mi++)
#pragma unroll
                for (int njj = 0; njj < 4; njj++) {
                    const int nj = njj >> 1, h = (njj & 1) * 2;
                    MMA16816(acc[mi][njj],
                             af[mi][0], af[mi][1], af[mi][2], af[mi][3],
                             bf[nj][h], bf[nj][h + 1]);
                }
        }
        // no trailing barrier: next iteration's barrier protects stage reuse
    }

    // epilogue: out = acc * x_scale[row] + bias[col]
#pragma unroll
    for (int mi = 0; mi < 4; mi++) {
        const int row0 = bm + warp_m * 64 + mi * 16 + (lane >> 2);
        const int row1 = row0 + 8;
        const float xs0 = g_xscale[row0];
        const float xs1 = g_xscale[row1];
        float* p0 = out + (size_t)row0 * O_DIM;
        float* p1 = out + (size_t)row1 * O_DIM;
#pragma unroll
        for (int njj = 0; njj < 4; njj++) {
            const int col = bn + warp_n * 32 + njj * 8 + (lane & 3) * 2;
            const float2 bv = *(const float2*)(bias + col);
            float2 o0, o1;
            o0.x = acc[mi][njj][0] * xs0 + bv.x;
            o0.y = acc[mi][njj][1] * xs0 + bv.y;
            o1.x = acc[mi][njj][2] * xs1 + bv.x;
            o1.y = acc[mi][njj][3] * xs1 + bv.y;
            *(float2*)(p0 + col) = o0;
            *(float2*)(p1 + col) = o1;
        }
    }
}

// ---------------------------------------------------------------------------
extern "C" void kernel_launch(void* const* d_in, const int* in_sizes, int n_in,
                              void* d_out, int out_size) {
    const float* x        = (const float*)d_in[0];
    const int*   qweight  = (const int*)d_in[1];
    const float* w_scales = (const float*)d_in[2];
    const int*   w_zp     = (const int*)d_in[3];
    const float* bias     = (const float*)d_in[4];
    float*       out      = (float*)d_out;

    quant_act_kernel<<<S_TOK, 256>>>(x);
    dequant_w_kernel<<<O_DIM, 256>>>(qweight, w_scales, w_zp);

    cudaFuncSetAttribute(gemm_f16_kernel,
                         cudaFuncAttributeMaxDynamicSharedMemorySize, GEMM_SMEM);
    const int grid = (S_TOK / BM) * (O_DIM / BN);   // 16 x 32 = 512
    gemm_f16_kernel<<<grid, THREADS, GEMM_SMEM>>>(bias, out);
}